// round 1
// baseline (speedup 1.0000x reference)
#include <cuda_runtime.h>
#include <math.h>

// Problem constants
#define BATCH 2048
#define TSEQ  512
#define ISZ   14
#define HID   128
#define G4    512          // 4*HID gate width
#define BT    16           // batch rows per CTA
#define NCTA  (BATCH/BT)   // 128
#define KC    32           // k-chunk for weight streaming
#define NTHR  256
#define SMEM_BYTES 181248

// Persistent device scratch (allowed: __device__ globals, no runtime alloc)
__device__ float g_WT[3][HID*G4];   // [0]=Whh0^T [1]=Wih1^T [2]=Whh1^T, layout [k][n]
__device__ float g_Wih0T[ISZ*G4];   // [k][n]
__device__ float g_b0[G4];
__device__ float g_b1[G4];

struct __align__(16) Smem {
    float ws0[ISZ][G4];    // 28672  resident Wih0^T
    float b0[G4];          // 2048
    float b1[G4];          // 2048
    float h0[BT][HID];     // 8192
    float h1[BT][HID];     // 8192
    float xs[BT][16];      // 1024 (14 used, padded)
    float wbuf[2][KC][G4]; // 131072 double-buffered weight chunks
};
static_assert(sizeof(Smem) == SMEM_BYTES, "smem layout");

// ---------------- setup: transpose weights, fuse biases -------------------
__global__ void setup_kernel(const float* __restrict__ Wih0, const float* __restrict__ Whh0,
                             const float* __restrict__ bih0, const float* __restrict__ bhh0,
                             const float* __restrict__ Wih1, const float* __restrict__ Whh1,
                             const float* __restrict__ bih1, const float* __restrict__ bhh1)
{
    int idx = blockIdx.x * blockDim.x + threadIdx.x;
    int stride = gridDim.x * blockDim.x;
    for (int t = idx; t < 3*HID*G4; t += stride) {
        int m = t / (HID*G4);
        int r = t % (HID*G4);
        int k = r / G4, n = r % G4;
        const float* src = (m == 0) ? Whh0 : (m == 1) ? Wih1 : Whh1;
        g_WT[m][r] = src[n*HID + k];
    }
    for (int t = idx; t < ISZ*G4; t += stride) {
        int k = t / G4, n = t % G4;
        g_Wih0T[t] = Wih0[n*ISZ + k];
    }
    for (int n = idx; n < G4; n += stride) {
        g_b0[n] = bih0[n] + bhh0[n];
        g_b1[n] = bih1[n] + bhh1[n];
    }
}

// ---------------- cp.async helpers ----------------------------------------
__device__ __forceinline__ unsigned smem_u32(const void* p) {
    return (unsigned)__cvta_generic_to_shared(p);
}
__device__ __forceinline__ void cp16(unsigned s, const void* g) {
    asm volatile("cp.async.cg.shared.global [%0], [%1], 16;\n" :: "r"(s), "l"(g));
}
__device__ __forceinline__ void cp4(unsigned s, const void* g) {
    asm volatile("cp.async.ca.shared.global [%0], [%1], 4;\n" :: "r"(s), "l"(g));
}
__device__ __forceinline__ void cp_commit() {
    asm volatile("cp.async.commit_group;\n");
}
__device__ __forceinline__ void cp_wait1() {
    asm volatile("cp.async.wait_group 1;\n");
}

__device__ __forceinline__ void issue_w(Smem& sm, int logical, int buf, int tid) {
    const float* src = &g_WT[logical >> 2][(logical & 3) * KC * G4];
    unsigned d = smem_u32(&sm.wbuf[buf][0][0]) + (unsigned)tid * 16u;
    const char* s = (const char*)src + tid * 16;
    #pragma unroll
    for (int i = 0; i < (KC*G4*4)/(NTHR*16); i++)   // 16 iters
        cp16(d + i*NTHR*16, s + i*NTHR*16);
}

__device__ __forceinline__ void issue_xs(Smem& sm, const float* __restrict__ x,
                                         int b0i, int t, int tid) {
    if (tid < BT*ISZ) {
        int rb = tid / ISZ, kk = tid % ISZ;
        cp4(smem_u32(&sm.xs[rb][kk]),
            x + (size_t)(b0i + rb) * TSEQ * ISZ + (size_t)t * ISZ + kk);
    }
}

__device__ __forceinline__ float sigmoidf_(float v) {
    return 1.0f / (1.0f + __expf(-v));
}

// ---------------- fused persistent 2-layer LSTM ---------------------------
__global__ void __launch_bounds__(NTHR, 1)
lstm_fused_kernel(const float* __restrict__ x, const float* __restrict__ Wfc,
                  const float* __restrict__ bfc, float* __restrict__ out)
{
    extern __shared__ float smem_raw[];
    Smem& sm = *reinterpret_cast<Smem*>(smem_raw);
    const int tid = threadIdx.x;
    const int b0i = blockIdx.x * BT;
    const int bg  = tid >> 6;   // 0..3 -> rows 4*bg..4*bg+3
    const int jg  = tid & 63;   // j = 2*jg, 2*jg+1

    // resident smem loads + zero states
    for (int i = tid; i < ISZ*G4; i += NTHR) (&sm.ws0[0][0])[i] = g_Wih0T[i];
    for (int i = tid; i < G4; i += NTHR) { sm.b0[i] = g_b0[i]; sm.b1[i] = g_b1[i]; }
    for (int i = tid; i < BT*HID; i += NTHR) { (&sm.h0[0][0])[i] = 0.f; (&sm.h1[0][0])[i] = 0.f; }

    float c0[2][4] = {{0.f,0.f,0.f,0.f},{0.f,0.f,0.f,0.f}};
    float c1[2][4] = {{0.f,0.f,0.f,0.f},{0.f,0.f,0.f,0.f}};
    float acc[4][2][4];

    // prime pipeline: chunk 0 of Whh0 (-> buf 0) + x inputs for t=0
    issue_w(sm, 0, 0, tid);
    issue_xs(sm, x, b0i, 0, tid);
    cp_commit();

    for (int t = 0; t < TSEQ; ++t) {
        #pragma unroll 1
        for (int p = 0; p < 12; ++p) {
            // issue next chunk (or next step's chunk 0 + next x row)
            if (p < 11) {
                issue_w(sm, p + 1, (p + 1) & 1, tid);
            } else if (t + 1 < TSEQ) {
                issue_w(sm, 0, 0, tid);
                issue_xs(sm, x, b0i, t + 1, tid);
            }
            cp_commit();
            cp_wait1();          // chunk p has landed
            __syncthreads();

            if (p == 0) {
                // acc = bias0 + x[t] @ Wih0^T  (K=14 resident in smem)
                #pragma unroll
                for (int g = 0; g < 4; g++) {
                    float2 bv = *(const float2*)&sm.b0[g*HID + 2*jg];
                    #pragma unroll
                    for (int bb = 0; bb < 4; bb++) { acc[g][0][bb] = bv.x; acc[g][1][bb] = bv.y; }
                }
                #pragma unroll
                for (int kk = 0; kk < ISZ; kk++) {
                    float v0 = sm.xs[4*bg+0][kk];
                    float v1 = sm.xs[4*bg+1][kk];
                    float v2 = sm.xs[4*bg+2][kk];
                    float v3 = sm.xs[4*bg+3][kk];
                    #pragma unroll
                    for (int g = 0; g < 4; g++) {
                        float2 w = *(const float2*)&sm.ws0[kk][g*HID + 2*jg];
                        acc[g][0][0] += w.x*v0; acc[g][0][1] += w.x*v1;
                        acc[g][0][2] += w.x*v2; acc[g][0][3] += w.x*v3;
                        acc[g][1][0] += w.y*v0; acc[g][1][1] += w.y*v1;
                        acc[g][1][2] += w.y*v2; acc[g][1][3] += w.y*v3;
                    }
                }
            } else if (p == 4) {
                #pragma unroll
                for (int g = 0; g < 4; g++) {
                    float2 bv = *(const float2*)&sm.b1[g*HID + 2*jg];
                    #pragma unroll
                    for (int bb = 0; bb < 4; bb++) { acc[g][0][bb] = bv.x; acc[g][1][bb] = bv.y; }
                }
            }

            // GEMM chunk p: acc += A[:, k0:k0+32] @ W^T chunk
            // p 0-3: Whh0 * h0(old) | p 4-7: Wih1 * h0(new) | p 8-11: Whh1 * h1(old)
            {
                const float (*A)[HID] = (p < 8) ? sm.h0 : sm.h1;
                const int k0 = (p & 3) * KC;
                const float* a0 = &A[4*bg+0][k0];
                const float* a1 = &A[4*bg+1][k0];
                const float* a2 = &A[4*bg+2][k0];
                const float* a3 = &A[4*bg+3][k0];
                const float (*ws)[G4] = sm.wbuf[p & 1];
                #pragma unroll 8
                for (int kk = 0; kk < KC; kk++) {
                    float v0 = a0[kk], v1 = a1[kk], v2 = a2[kk], v3 = a3[kk];
                    #pragma unroll
                    for (int g = 0; g < 4; g++) {
                        float2 w = *(const float2*)&ws[kk][g*HID + 2*jg];
                        acc[g][0][0] += w.x*v0; acc[g][0][1] += w.x*v1;
                        acc[g][0][2] += w.x*v2; acc[g][0][3] += w.x*v3;
                        acc[g][1][0] += w.y*v0; acc[g][1][1] += w.y*v1;
                        acc[g][1][2] += w.y*v2; acc[g][1][3] += w.y*v3;
                    }
                }
            }
            __syncthreads();

            if (p == 3) {
                // layer-0 elementwise; thread-local (owns all 4 gates of its j's)
                #pragma unroll
                for (int jj = 0; jj < 2; jj++)
                #pragma unroll
                for (int bb = 0; bb < 4; bb++) {
                    float ig = sigmoidf_(acc[0][jj][bb]);
                    float fg = sigmoidf_(acc[1][jj][bb]);
                    float gg = tanhf(acc[2][jj][bb]);
                    float og = sigmoidf_(acc[3][jj][bb]);
                    float c  = fg * c0[jj][bb] + ig * gg;
                    c0[jj][bb] = c;
                    sm.h0[4*bg+bb][2*jg+jj] = og * tanhf(c);
                }
            } else if (p == 11) {
                #pragma unroll
                for (int jj = 0; jj < 2; jj++)
                #pragma unroll
                for (int bb = 0; bb < 4; bb++) {
                    float ig = sigmoidf_(acc[0][jj][bb]);
                    float fg = sigmoidf_(acc[1][jj][bb]);
                    float gg = tanhf(acc[2][jj][bb]);
                    float og = sigmoidf_(acc[3][jj][bb]);
                    float c  = fg * c1[jj][bb] + ig * gg;
                    c1[jj][bb] = c;
                    sm.h1[4*bg+bb][2*jg+jj] = og * tanhf(c);
                }
            }
        }
    }
    __syncthreads();

    // FC + sigmoid on final h1: out[b] = sigmoid(h1[b] . Wfc + bfc)
    {
        const int w = tid >> 5, l = tid & 31;
        float bias = bfc[0];
        for (int r = w; r < BT; r += NTHR/32) {
            float s = 0.f;
            #pragma unroll
            for (int kk = 0; kk < HID/32; kk++)
                s += sm.h1[r][l + kk*32] * Wfc[l + kk*32];
            #pragma unroll
            for (int off = 16; off; off >>= 1)
                s += __shfl_xor_sync(0xffffffffu, s, off);
            if (l == 0)
                out[b0i + r] = 1.0f / (1.0f + __expf(-(s + bias)));
        }
    }
}

// ---------------- launch ---------------------------------------------------
extern "C" void kernel_launch(void* const* d_in, const int* in_sizes, int n_in,
                              void* d_out, int out_size)
{
    const float* x    = (const float*)d_in[0];
    const float* Wih0 = (const float*)d_in[1];
    const float* Whh0 = (const float*)d_in[2];
    const float* bih0 = (const float*)d_in[3];
    const float* bhh0 = (const float*)d_in[4];
    const float* Wih1 = (const float*)d_in[5];
    const float* Whh1 = (const float*)d_in[6];
    const float* bih1 = (const float*)d_in[7];
    const float* bhh1 = (const float*)d_in[8];
    const float* Wfc  = (const float*)d_in[9];
    const float* bfc  = (const float*)d_in[10];

    cudaFuncSetAttribute(lstm_fused_kernel,
                         cudaFuncAttributeMaxDynamicSharedMemorySize, SMEM_BYTES);

    setup_kernel<<<96, 256>>>(Wih0, Whh0, bih0, bhh0, Wih1, Whh1, bih1, bhh1);
    lstm_fused_kernel<<<NCTA, NTHR, SMEM_BYTES>>>(x, Wfc, bfc, (float*)d_out);
}

// round 2
// speedup vs baseline: 1.1292x; 1.1292x over previous
#include <cuda_runtime.h>

#define BATCH 2048
#define TSEQ  512
#define ISZ   14
#define HID   128
#define G4    512          // 4*HID
#define BT    16           // batch rows per CTA
#define NCTA  (BATCH/BT)   // 128
#define KC    32           // k-chunk for weight streaming
#define NTHR  256
#define HSTR  18           // padded row stride (floats) for transposed h

typedef unsigned long long ull;

// Persistent device scratch
__device__ float g_WT[3][HID*G4];   // [0]=Whh0^T [1]=Wih1^T [2]=Whh1^T, layout [k][n]
__device__ float g_Wih0T[ISZ*G4];   // [k][n]
__device__ float g_b0[G4];
__device__ float g_b1[G4];

struct __align__(16) Smem {
    float ws0[ISZ][G4];     // 28672 resident Wih0^T
    float b0[G4];           // 2048
    float b1[G4];           // 2048
    float hT0[HID][HSTR];   // 9216  transposed h, layer 0: [unit][row]
    float hT1[HID][HSTR];   // 9216  transposed h, layer 1
    float xsT[16][HSTR];    // 1152  transposed x slice: [k][row]
    float wbuf[2][KC][G4];  // 131072 double-buffered weight chunks
};

// ---------------- setup: transpose weights, fuse biases -------------------
__global__ void setup_kernel(const float* __restrict__ Wih0, const float* __restrict__ Whh0,
                             const float* __restrict__ bih0, const float* __restrict__ bhh0,
                             const float* __restrict__ Wih1, const float* __restrict__ Whh1,
                             const float* __restrict__ bih1, const float* __restrict__ bhh1)
{
    int idx = blockIdx.x * blockDim.x + threadIdx.x;
    int stride = gridDim.x * blockDim.x;
    for (int t = idx; t < 3*HID*G4; t += stride) {
        int m = t / (HID*G4);
        int r = t % (HID*G4);
        int k = r / G4, n = r % G4;
        const float* src = (m == 0) ? Whh0 : (m == 1) ? Wih1 : Whh1;
        g_WT[m][r] = src[n*HID + k];
    }
    for (int t = idx; t < ISZ*G4; t += stride) {
        int k = t / G4, n = t % G4;
        g_Wih0T[t] = Wih0[n*ISZ + k];
    }
    for (int n = idx; n < G4; n += stride) {
        g_b0[n] = bih0[n] + bhh0[n];
        g_b1[n] = bih1[n] + bhh1[n];
    }
}

// ---------------- small helpers -------------------------------------------
__device__ __forceinline__ unsigned smem_u32(const void* p) {
    return (unsigned)__cvta_generic_to_shared(p);
}
__device__ __forceinline__ void cp16(unsigned s, const void* g) {
    asm volatile("cp.async.cg.shared.global [%0], [%1], 16;\n" :: "r"(s), "l"(g));
}
__device__ __forceinline__ void cp4(unsigned s, const void* g) {
    asm volatile("cp.async.ca.shared.global [%0], [%1], 4;\n" :: "r"(s), "l"(g));
}
__device__ __forceinline__ void cp_commit() {
    asm volatile("cp.async.commit_group;\n");
}
__device__ __forceinline__ void cp_wait1() {
    asm volatile("cp.async.wait_group 1;\n");
}

__device__ __forceinline__ ull pk2(float v) {          // {v, v}
    ull r; asm("mov.b64 %0, {%1, %1};" : "=l"(r) : "f"(v)); return r;
}
__device__ __forceinline__ void fma2(ull& d, ull a, ull b) {  // d += a*b (f32x2)
    asm("fma.rn.f32x2 %0, %1, %2, %0;" : "+l"(d) : "l"(a), "l"(b));
}
__device__ __forceinline__ float2 up(ull v) {
    float2 r; asm("mov.b64 {%0, %1}, %2;" : "=f"(r.x), "=f"(r.y) : "l"(v)); return r;
}
__device__ __forceinline__ float sigf(float x) {
    return __fdividef(1.0f, 1.0f + __expf(-x));
}
__device__ __forceinline__ float tanhfast(float x) {
    return 1.0f - __fdividef(2.0f, __expf(2.0f*x) + 1.0f);
}

__device__ __forceinline__ void issue_w(Smem& sm, int logical, int buf, int tid) {
    const float* src = &g_WT[logical >> 2][(logical & 3) * KC * G4];
    unsigned d = smem_u32(&sm.wbuf[buf][0][0]) + (unsigned)tid * 16u;
    const char* s = (const char*)src + tid * 16;
    #pragma unroll
    for (int i = 0; i < (KC*G4*4)/(NTHR*16); i++)   // 16 iters
        cp16(d + i*NTHR*16, s + i*NTHR*16);
}

__device__ __forceinline__ void issue_xs(Smem& sm, const float* __restrict__ x,
                                         int b0i, int t, int tid) {
    if (tid < BT*ISZ) {   // 224 threads
        int rb = tid & 15, kk = tid >> 4;
        cp4(smem_u32(&sm.xsT[kk][rb]),
            x + (size_t)(b0i + rb) * TSEQ * ISZ + (size_t)t * ISZ + kk);
    }
}

// ---------------- packed GEMM chunk ---------------------------------------
// acc[g][rp] (f32x2 over row pairs) += ws[kk][g*HID+jg] * hT[kk][r0 + 2rp..]
__device__ __forceinline__ void gemm_chunk(const float (*__restrict__ ws)[G4],
                                           const float (*__restrict__ hT)[HSTR],
                                           int jg, int r0, ull acc[4][4], int nk)
{
    #pragma unroll 4
    for (int kk = 0; kk < nk; kk++) {
        const float* hrow = &hT[kk][r0];
        ull a0 = *(const ull*)(hrow + 0);
        ull a1 = *(const ull*)(hrow + 2);
        ull a2 = *(const ull*)(hrow + 4);
        ull a3 = *(const ull*)(hrow + 6);
        const float* wr = &ws[kk][jg];
        ull w0 = pk2(wr[0*HID]);
        ull w1 = pk2(wr[1*HID]);
        ull w2 = pk2(wr[2*HID]);
        ull w3 = pk2(wr[3*HID]);
        fma2(acc[0][0], w0, a0); fma2(acc[0][1], w0, a1);
        fma2(acc[0][2], w0, a2); fma2(acc[0][3], w0, a3);
        fma2(acc[1][0], w1, a0); fma2(acc[1][1], w1, a1);
        fma2(acc[1][2], w1, a2); fma2(acc[1][3], w1, a3);
        fma2(acc[2][0], w2, a0); fma2(acc[2][1], w2, a1);
        fma2(acc[2][2], w2, a2); fma2(acc[2][3], w2, a3);
        fma2(acc[3][0], w3, a0); fma2(acc[3][1], w3, a1);
        fma2(acc[3][2], w3, a2); fma2(acc[3][3], w3, a3);
    }
}

// ---------------- LSTM elementwise (8 rows of one hidden unit) ------------
__device__ __forceinline__ void lstm_cell(ull acc[4][4], float* cst, float* hdst)
{
    #pragma unroll
    for (int rp = 0; rp < 4; rp++) {
        float2 gi = up(acc[0][rp]);
        float2 gf = up(acc[1][rp]);
        float2 gg = up(acc[2][rp]);
        float2 go = up(acc[3][rp]);
        {
            float c = sigf(gf.x)*cst[2*rp] + sigf(gi.x)*tanhfast(gg.x);
            cst[2*rp] = c;
            hdst[2*rp] = sigf(go.x)*tanhfast(c);
        }
        {
            float c = sigf(gf.y)*cst[2*rp+1] + sigf(gi.y)*tanhfast(gg.y);
            cst[2*rp+1] = c;
            hdst[2*rp+1] = sigf(go.y)*tanhfast(c);
        }
    }
}

// ---------------- fused persistent 2-layer LSTM ---------------------------
__global__ void __launch_bounds__(NTHR, 1)
lstm_fused_kernel(const float* __restrict__ x, const float* __restrict__ Wfc,
                  const float* __restrict__ bfc, float* __restrict__ out)
{
    extern __shared__ float smem_raw[];
    Smem& sm = *reinterpret_cast<Smem*>(smem_raw);
    const int tid = threadIdx.x;
    const int b0i = blockIdx.x * BT;
    const int jg  = tid & 127;        // hidden unit owned by this thread
    const int r0  = (tid >> 7) * 8;   // first of 8 batch rows

    for (int i = tid; i < ISZ*G4; i += NTHR) (&sm.ws0[0][0])[i] = g_Wih0T[i];
    for (int i = tid; i < G4; i += NTHR) { sm.b0[i] = g_b0[i]; sm.b1[i] = g_b1[i]; }
    for (int i = tid; i < HID*HSTR; i += NTHR) { (&sm.hT0[0][0])[i] = 0.f; (&sm.hT1[0][0])[i] = 0.f; }

    float c0s[8], c1s[8];
    #pragma unroll
    for (int i = 0; i < 8; i++) { c0s[i] = 0.f; c1s[i] = 0.f; }

    ull acc[4][4];

    // prime pipeline: chunk 0 of Whh0 (-> buf 0) + x inputs for t=0
    issue_w(sm, 0, 0, tid);
    issue_xs(sm, x, b0i, 0, tid);
    cp_commit();

    for (int t = 0; t < TSEQ; ++t) {
        #pragma unroll 1
        for (int p = 0; p < 12; ++p) {
            if (p < 11) {
                issue_w(sm, p + 1, (p + 1) & 1, tid);
            } else if (t + 1 < TSEQ) {
                issue_w(sm, 0, 0, tid);
                issue_xs(sm, x, b0i, t + 1, tid);
            }
            cp_commit();
            cp_wait1();          // chunk p has landed (this thread)
            __syncthreads();     // visibility of all threads' cp.async data

            if (p == 0) {
                #pragma unroll
                for (int g = 0; g < 4; g++) {
                    ull bv = pk2(sm.b0[g*HID + jg]);
                    acc[g][0] = bv; acc[g][1] = bv; acc[g][2] = bv; acc[g][3] = bv;
                }
                // x projection: K=14 resident in smem
                gemm_chunk(sm.ws0, sm.xsT, jg, r0, acc, ISZ);
            } else if (p == 4) {
                #pragma unroll
                for (int g = 0; g < 4; g++) {
                    ull bv = pk2(sm.b1[g*HID + jg]);
                    acc[g][0] = bv; acc[g][1] = bv; acc[g][2] = bv; acc[g][3] = bv;
                }
            }

            // GEMM chunk p: p 0-3: Whh0*h0(old) | 4-7: Wih1*h0(new) | 8-11: Whh1*h1(old)
            gemm_chunk(sm.wbuf[p & 1],
                       ((p < 8) ? sm.hT0 : sm.hT1) + (p & 3) * KC,
                       jg, r0, acc, KC);

            __syncthreads();     // separate gemm reads from state writes / buffer reuse

            if (p == 3)       lstm_cell(acc, c0s, &sm.hT0[jg][r0]);
            else if (p == 11) lstm_cell(acc, c1s, &sm.hT1[jg][r0]);
        }
    }
    __syncthreads();

    // FC + sigmoid on final h1: out[b] = sigmoid(h1[b] . Wfc + bfc)
    {
        const int w = tid >> 5, l = tid & 31;
        float bias = bfc[0];
        for (int r = w; r < BT; r += NTHR/32) {
            float s = 0.f;
            #pragma unroll
            for (int kk = 0; kk < HID/32; kk++)
                s += sm.hT1[l + kk*32][r] * Wfc[l + kk*32];
            #pragma unroll
            for (int off = 16; off; off >>= 1)
                s += __shfl_xor_sync(0xffffffffu, s, off);
            if (l == 0)
                out[b0i + r] = sigf(s + bias);
        }
    }
}

// ---------------- launch ---------------------------------------------------
extern "C" void kernel_launch(void* const* d_in, const int* in_sizes, int n_in,
                              void* d_out, int out_size)
{
    const float* x    = (const float*)d_in[0];
    const float* Wih0 = (const float*)d_in[1];
    const float* Whh0 = (const float*)d_in[2];
    const float* bih0 = (const float*)d_in[3];
    const float* bhh0 = (const float*)d_in[4];
    const float* Wih1 = (const float*)d_in[5];
    const float* Whh1 = (const float*)d_in[6];
    const float* bih1 = (const float*)d_in[7];
    const float* bhh1 = (const float*)d_in[8];
    const float* Wfc  = (const float*)d_in[9];
    const float* bfc  = (const float*)d_in[10];

    cudaFuncSetAttribute(lstm_fused_kernel,
                         cudaFuncAttributeMaxDynamicSharedMemorySize, (int)sizeof(Smem));

    setup_kernel<<<96, 256>>>(Wih0, Whh0, bih0, bhh0, Wih1, Whh1, bih1, bhh1);
    lstm_fused_kernel<<<NCTA, NTHR, sizeof(Smem)>>>(x, Wfc, bfc, (float*)d_out);
}